// round 7
// baseline (speedup 1.0000x reference)
#include <cuda_runtime.h>
#include <cuda_bf16.h>
#include <math.h>
#include <stdint.h>

// Problem constants
#define BQ   16
#define NQ   8192
#define SQ   2048
#define C1Q  128
#define C2Q  256
#define PQ   (BQ * NQ)      // 131072 points
#define KX   384            // C1 + C2 (GEMM1 K)
#define M0Q  256            // layer0 out channels
#define M1Q  128            // layer1 out channels
#define BN_EPS 1e-5f

// ---------------- scratch (static device globals; no cudaMalloc) ------------
__device__ float g_b0f[M0Q];
__device__ float g_b1f[M1Q];
__device__ __nv_bfloat16 g_w0hi[M0Q * KX];
__device__ __nv_bfloat16 g_w0lo[M0Q * KX];
__device__ __nv_bfloat16 g_w1hi[M1Q * M0Q];
__device__ __nv_bfloat16 g_w1lo[M1Q * M0Q];
__device__ float g_f2t[BQ * SQ * C2Q];                  // features_2 transposed [b][s][c]
__device__ __nv_bfloat16 g_xhi[(size_t)PQ * KX];        // X hi, K-major [p][k]
__device__ __nv_bfloat16 g_xlo[(size_t)PQ * KX];
__device__ __nv_bfloat16 g_yhi[(size_t)PQ * M0Q];       // Y hi, K-major [p][m]
__device__ __nv_bfloat16 g_ylo[(size_t)PQ * M0Q];

// ---------------- PTX helpers (sm_80-level only; NO tcgen05) ----------------
__device__ __forceinline__ uint32_t smem_u32(const void* p) {
    uint32_t r;
    asm("{ .reg .u64 t; cvta.to.shared.u64 t, %1; cvt.u32.u64 %0, t; }" : "=r"(r) : "l"(p));
    return r;
}
__device__ __forceinline__ void cp16(uint32_t dst, const void* src) {
    asm volatile("cp.async.cg.shared.global [%0], [%1], 16;" :: "r"(dst), "l"(src));
}
#define CP_COMMIT() asm volatile("cp.async.commit_group;" ::: "memory")
#define CP_WAIT0()  asm volatile("cp.async.wait_group 0;" ::: "memory")
#define CP_WAIT1()  asm volatile("cp.async.wait_group 1;" ::: "memory")

#define SWZ(o) ((uint32_t)(o) ^ ((((uint32_t)(o)) >> 3) & 0x70u))

__device__ __forceinline__ void ldsm4(uint32_t& r0, uint32_t& r1, uint32_t& r2,
                                      uint32_t& r3, uint32_t addr) {
    asm volatile("ldmatrix.sync.aligned.m8n8.x4.shared.b16 {%0,%1,%2,%3}, [%4];"
                 : "=r"(r0), "=r"(r1), "=r"(r2), "=r"(r3) : "r"(addr));
}
__device__ __forceinline__ void mma16816(float* d, uint32_t a0, uint32_t a1,
                                         uint32_t a2, uint32_t a3,
                                         uint32_t b0, uint32_t b1) {
    asm volatile(
        "mma.sync.aligned.m16n8k16.row.col.f32.bf16.bf16.f32 "
        "{%0,%1,%2,%3}, {%4,%5,%6,%7}, {%8,%9}, {%0,%1,%2,%3};"
        : "+f"(d[0]), "+f"(d[1]), "+f"(d[2]), "+f"(d[3])
        : "r"(a0), "r"(a1), "r"(a2), "r"(a3), "r"(b0), "r"(b1));
}

__device__ __forceinline__ void split_pack(float v0, float v1, uint32_t& ph, uint32_t& plo) {
    __nv_bfloat16 h0 = __float2bfloat16(v0), h1 = __float2bfloat16(v1);
    float r0 = v0 - __bfloat162float(h0), r1 = v1 - __bfloat162float(h1);
    __nv_bfloat16 l0 = __float2bfloat16(r0), l1 = __float2bfloat16(r1);
    ph  = (uint32_t)__bfloat16_as_ushort(h0) | ((uint32_t)__bfloat16_as_ushort(h1) << 16);
    plo = (uint32_t)__bfloat16_as_ushort(l0) | ((uint32_t)__bfloat16_as_ushort(l1) << 16);
}

// ---------------- BN fold + bf16 split ---------------------------------------
__global__ void fold0_kernel(const float* __restrict__ w, const float* __restrict__ b,
                             const float* __restrict__ g, const float* __restrict__ be,
                             const float* __restrict__ m, const float* __restrict__ v) {
    int o = blockIdx.x;
    float s = g[o] * rsqrtf(v[o] + BN_EPS);
    int c = threadIdx.x;
    float val = w[o * KX + c] * s;
    __nv_bfloat16 hi = __float2bfloat16(val);
    g_w0hi[o * KX + c] = hi;
    g_w0lo[o * KX + c] = __float2bfloat16(val - __bfloat162float(hi));
    if (c == 0) g_b0f[o] = (b[o] - m[o]) * s + be[o];
}

__global__ void fold1_kernel(const float* __restrict__ w, const float* __restrict__ b,
                             const float* __restrict__ g, const float* __restrict__ be,
                             const float* __restrict__ m, const float* __restrict__ v) {
    int o = blockIdx.x;
    float s = g[o] * rsqrtf(v[o] + BN_EPS);
    int c = threadIdx.x;
    float val = w[o * M0Q + c] * s;
    __nv_bfloat16 hi = __float2bfloat16(val);
    g_w1hi[o * M0Q + c] = hi;
    g_w1lo[o * M0Q + c] = __float2bfloat16(val - __bfloat162float(hi));
    if (c == 0) g_b1f[o] = (b[o] - m[o]) * s + be[o];
}

// ---------------- transpose features_2: (B,C2,S) -> (B,S,C2) ----------------
__global__ void transpose_f2_kernel(const float* __restrict__ f2) {
    __shared__ float tile[32][33];
    int b  = blockIdx.z;
    int s0 = blockIdx.x * 32;
    int c0 = blockIdx.y * 32;
    int s = s0 + threadIdx.x;
#pragma unroll
    for (int r = 0; r < 4; r++) {
        int c = c0 + threadIdx.y + r * 8;
        tile[threadIdx.y + r * 8][threadIdx.x] = f2[((size_t)b * C2Q + c) * SQ + s];
    }
    __syncthreads();
    int c = c0 + threadIdx.x;
#pragma unroll
    for (int r = 0; r < 4; r++) {
        int s2 = s0 + threadIdx.y + r * 8;
        g_f2t[((size_t)b * SQ + s2) * C2Q + c] = tile[threadIdx.x][threadIdx.y + r * 8];
    }
}

// ---------------- features_1 -> X[p][0..127] bf16 hi/lo ----------------------
__global__ __launch_bounds__(256) void copy_f1_kernel(const float* __restrict__ f1) {
    __shared__ float tile[C1Q][33];
    int b  = blockIdx.y;
    int n0 = blockIdx.x * 32;
    int tid = threadIdx.x;
#pragma unroll
    for (int it = 0; it < 16; it++) {
        int i = tid + it * 256;
        int c = i >> 5, n = i & 31;
        tile[c][n] = f1[((size_t)b * C1Q + c) * NQ + n0 + n];
    }
    __syncthreads();
    uint32_t* xhi = (uint32_t*)g_xhi;
    uint32_t* xlo = (uint32_t*)g_xlo;
#pragma unroll
    for (int it = 0; it < 8; it++) {
        int i = tid + it * 256;
        int nrow = i >> 6, c2 = i & 63;
        uint32_t ph, plo;
        split_pack(tile[c2 * 2][nrow], tile[c2 * 2 + 1][nrow], ph, plo);
        size_t p = (size_t)b * NQ + n0 + nrow;
        xhi[p * (KX / 2) + c2] = ph;
        xlo[p * (KX / 2) + c2] = plo;
    }
}

// ---------------- fused 3-NN + gather/interpolate -> X[p][128..383] ----------
// Phase 1: each of 256 threads finds 3-NN for its point (reference rounding;
// results stay in SMEM). Phase 2: 8 sub-blocks of 32 points gather features_2
// coalesced, interpolate, and store bf16 hi/lo K-major.
__global__ __launch_bounds__(256) void knng_kernel(const float* __restrict__ c1,
                                                   const float* __restrict__ c2) {
    extern __shared__ char km[];
    float4* sc = (float4*)km;                                   // [2048]  32768 B
    float (*tile)[257] = (float(*)[257])(km + 32768);           // 32*257*4 = 32896 B
    int*   sidx = (int*)(km + 32768 + 32896);                   // 256*3*4 = 3072 B
    float* swt  = (float*)(km + 32768 + 32896 + 3072);          // 3072 B

    const int tid = threadIdx.x;
    const int b   = blockIdx.x >> 5;
    const int n0  = (blockIdx.x & 31) * 256;

    // ---- phase 1: knn ----
    const float* cb = c2 + (size_t)b * 3 * SQ;
    for (int i = tid; i < SQ; i += 256) {
        float x = cb[i], y = cb[SQ + i], z = cb[2 * SQ + i];
        float sq = __fadd_rn(__fadd_rn(__fmul_rn(x, x), __fmul_rn(y, y)), __fmul_rn(z, z));
        sc[i] = make_float4(x, y, z, sq);
    }
    __syncthreads();

    {
        int n = n0 + tid;
        const float* qb = c1 + (size_t)b * 3 * NQ;
        float x1 = qb[n], y1 = qb[NQ + n], z1 = qb[2 * NQ + n];
        float q2 = __fadd_rn(__fadd_rn(__fmul_rn(x1, x1), __fmul_rn(y1, y1)), __fmul_rn(z1, z1));

        float d0 = 1e30f, d1 = 1e30f, d2 = 1e30f;
        int   i0 = 0, i1 = 0, i2 = 0;
#pragma unroll 4
        for (int s = 0; s < SQ; s++) {
            float4 c = sc[s];
            float dot = __fadd_rn(__fadd_rn(__fmul_rn(x1, c.x), __fmul_rn(y1, c.y)),
                                  __fmul_rn(z1, c.z));
            float d = __fsub_rn(__fadd_rn(q2, c.w), __fadd_rn(dot, dot));
            if (d < d2) {
                if (d < d1) {
                    d2 = d1; i2 = i1;
                    if (d < d0) { d1 = d0; i1 = i0; d0 = d; i0 = s; }
                    else        { d1 = d;  i1 = s; }
                } else { d2 = d; i2 = s; }
            }
        }
        d0 = fmaxf(d0, 1e-10f); d1 = fmaxf(d1, 1e-10f); d2 = fmaxf(d2, 1e-10f);
        float r0 = __fdiv_rn(1.0f, d0), r1 = __fdiv_rn(1.0f, d1), r2 = __fdiv_rn(1.0f, d2);
        float rs = __fadd_rn(__fadd_rn(r0, r1), r2);
        sidx[tid * 3 + 0] = i0; sidx[tid * 3 + 1] = i1; sidx[tid * 3 + 2] = i2;
        swt[tid * 3 + 0] = __fdiv_rn(r0, rs);
        swt[tid * 3 + 1] = __fdiv_rn(r1, rs);
        swt[tid * 3 + 2] = __fdiv_rn(r2, rs);
    }
    __syncthreads();

    // ---- phase 2: gather + interpolate, 8 sub-blocks of 32 points ----
    const int warp = tid >> 5, lane = tid & 31;
    const float* fbase = g_f2t + (size_t)b * SQ * C2Q;
    uint32_t* xhi = (uint32_t*)g_xhi;
    uint32_t* xlo = (uint32_t*)g_xlo;

    for (int sb = 0; sb < 8; sb++) {
        const int pb = sb * 32;
#pragma unroll
        for (int it = 0; it < 4; it++) {
            int pl = warp * 4 + it;
            int lp = pb + pl;
            const float* fa = fbase + (size_t)sidx[lp * 3 + 0] * C2Q;
            const float* fb = fbase + (size_t)sidx[lp * 3 + 1] * C2Q;
            const float* fc = fbase + (size_t)sidx[lp * 3 + 2] * C2Q;
            float w0 = swt[lp * 3 + 0], w1 = swt[lp * 3 + 1], w2 = swt[lp * 3 + 2];
#pragma unroll
            for (int q = 0; q < 2; q++) {
                int c = lane * 4 + q * 128;
                float4 a = *(const float4*)(fa + c);
                float4 bb = *(const float4*)(fb + c);
                float4 cv = *(const float4*)(fc + c);
                tile[pl][c + 0] = __fadd_rn(__fadd_rn(__fmul_rn(a.x, w0), __fmul_rn(bb.x, w1)), __fmul_rn(cv.x, w2));
                tile[pl][c + 1] = __fadd_rn(__fadd_rn(__fmul_rn(a.y, w0), __fmul_rn(bb.y, w1)), __fmul_rn(cv.y, w2));
                tile[pl][c + 2] = __fadd_rn(__fadd_rn(__fmul_rn(a.z, w0), __fmul_rn(bb.z, w1)), __fmul_rn(cv.z, w2));
                tile[pl][c + 3] = __fadd_rn(__fadd_rn(__fmul_rn(a.w, w0), __fmul_rn(bb.w, w1)), __fmul_rn(cv.w, w2));
            }
        }
        __syncthreads();
#pragma unroll
        for (int it = 0; it < 16; it++) {
            int i = tid + it * 256;
            int pl = i >> 7, c2 = i & 127;
            uint32_t ph, plo;
            split_pack(tile[pl][c2 * 2], tile[pl][c2 * 2 + 1], ph, plo);
            size_t p = (size_t)b * NQ + n0 + pb + pl;
            xhi[p * (KX / 2) + 64 + c2] = ph;
            xlo[p * (KX / 2) + 64 + c2] = plo;
        }
        __syncthreads();
    }
}

// ---------------- mma.sync bf16x3 GEMM (512 threads, 16 warps) ---------------
// out[p][n] = relu(sum_k A[p][k]*W[n][k] + bias[n]) via
// D = Ahi*Whi + Alo*Whi + Ahi*Wlo, fp32 accumulate.
// CTA tile: 128 points x 128 channels, K chunk = 64 bf16 (SW128 SMEM),
// cp.async double-buffered. 16 warps as 4(m) x 4(n); warp tile 32x32.
template <int KDIM, bool FINAL>
__global__ __launch_bounds__(512, 1) void mma_gemm_kernel(float* __restrict__ outF) {
    constexpr int NCH   = KDIM / 64;
    constexpr int TILE  = 128 * 64 * 2;      // 16 KB per matrix half-chunk
    constexpr int CHUNK = 4 * TILE;          // Ahi, Alo, Whi, Wlo = 64 KB

    const __nv_bfloat16* Ahi = FINAL ? g_yhi : g_xhi;
    const __nv_bfloat16* Alo = FINAL ? g_ylo : g_xlo;
    const __nv_bfloat16* Whi = FINAL ? g_w1hi : g_w0hi;
    const __nv_bfloat16* Wlo = FINAL ? g_w1lo : g_w0lo;
    const float* bias = FINAL ? g_b1f : g_b0f;

    extern __shared__ __align__(1024) char dsm[];
    const uint32_t s0 = smem_u32(dsm);

    const int tid  = threadIdx.x;
    const int warp = tid >> 5;
    const int lane = tid & 31;
    const int wm   = warp >> 2;              // 0..3
    const int wn   = warp & 3;               // 0..3
    const int p0   = blockIdx.x * 128;
    const int n0   = blockIdx.y * 128;

    const int a_row = (lane & 15);
    const int a_k8  = (lane >> 4) * 8;
    const int b_row = ((lane >> 4) & 1) * 8 + (lane & 7);
    const int b_k8  = ((lane >> 3) & 1) * 8;

    float acc[2][4][4];
#pragma unroll
    for (int mi = 0; mi < 2; mi++)
#pragma unroll
        for (int ni = 0; ni < 4; ni++)
#pragma unroll
            for (int e = 0; e < 4; e++) acc[mi][ni][e] = 0.0f;

    auto load_chunk = [&](int buf, int ch) {
        const uint32_t base = s0 + buf * CHUNK;
        const size_t rs = (size_t)KDIM * 2;  // row stride bytes
        const char* gAh = (const char*)Ahi + (size_t)p0 * rs + (size_t)ch * 128;
        const char* gAl = (const char*)Alo + (size_t)p0 * rs + (size_t)ch * 128;
        const char* gWh = (const char*)Whi + (size_t)n0 * rs + (size_t)ch * 128;
        const char* gWl = (const char*)Wlo + (size_t)n0 * rs + (size_t)ch * 128;
#pragma unroll
        for (int it = 0; it < 2; it++) {
            int i = tid + it * 512;          // 0..1023
            int row = i >> 3, c16 = (i & 7) * 16;
            uint32_t sw = SWZ(row * 128 + c16);
            size_t go = (size_t)row * rs + c16;
            cp16(base + sw,            gAh + go);
            cp16(base + TILE + sw,     gAl + go);
            cp16(base + 2 * TILE + sw, gWh + go);
            cp16(base + 3 * TILE + sw, gWl + go);
        }
        CP_COMMIT();
    };

    load_chunk(0, 0);
    load_chunk(1, 1);

    for (int c = 0; c < NCH; c++) {
        if (c + 1 < NCH) { CP_WAIT1(); } else { CP_WAIT0(); }
        __syncthreads();

        const uint32_t base = s0 + (c & 1) * CHUNK;
#pragma unroll
        for (int kk = 0; kk < 4; kk++) {
            const int kb = (kk * 16 + a_k8) * 2;
            uint32_t ah[2][4], al[2][4];
#pragma unroll
            for (int mi = 0; mi < 2; mi++) {
                uint32_t off = SWZ((wm * 32 + mi * 16 + a_row) * 128 + kb);
                ldsm4(ah[mi][0], ah[mi][1], ah[mi][2], ah[mi][3], base + off);
                ldsm4(al[mi][0], al[mi][1], al[mi][2], al[mi][3], base + TILE + off);
            }
            uint32_t bh[4][2], bl[4][2];
            const int kbB = (kk * 16 + b_k8) * 2;
#pragma unroll
            for (int nip = 0; nip < 2; nip++) {
                uint32_t off = SWZ((wn * 32 + nip * 16 + b_row) * 128 + kbB);
                ldsm4(bh[2 * nip][0], bh[2 * nip][1], bh[2 * nip + 1][0], bh[2 * nip + 1][1],
                      base + 2 * TILE + off);
                ldsm4(bl[2 * nip][0], bl[2 * nip][1], bl[2 * nip + 1][0], bl[2 * nip + 1][1],
                      base + 3 * TILE + off);
            }
#pragma unroll
            for (int mi = 0; mi < 2; mi++)
#pragma unroll
                for (int ni = 0; ni < 4; ni++) {
                    mma16816(acc[mi][ni], ah[mi][0], ah[mi][1], ah[mi][2], ah[mi][3],
                             bh[ni][0], bh[ni][1]);
                    mma16816(acc[mi][ni], al[mi][0], al[mi][1], al[mi][2], al[mi][3],
                             bh[ni][0], bh[ni][1]);
                    mma16816(acc[mi][ni], ah[mi][0], ah[mi][1], ah[mi][2], ah[mi][3],
                             bl[ni][0], bl[ni][1]);
                }
        }

        if (c + 2 < NCH) {
            __syncthreads();
            load_chunk(c & 1, c + 2);
        }
    }

    // ---------------- epilogue -------------------------------------------------
    const int g = lane >> 2, t = lane & 3;
    if (!FINAL) {
        uint32_t* yhi = (uint32_t*)g_yhi;
        uint32_t* ylo = (uint32_t*)g_ylo;
#pragma unroll
        for (int mi = 0; mi < 2; mi++) {
#pragma unroll
            for (int ni = 0; ni < 4; ni++) {
                int col = n0 + wn * 32 + ni * 8 + t * 2;
                float bv0 = bias[col];
                float bv1 = bias[col + 1];
                int pr0 = p0 + wm * 32 + mi * 16 + g;
                float v0 = fmaxf(acc[mi][ni][0] + bv0, 0.f);
                float v1 = fmaxf(acc[mi][ni][1] + bv1, 0.f);
                uint32_t ph, plo;
                split_pack(v0, v1, ph, plo);
                size_t d0 = (size_t)pr0 * (M0Q / 2) + (col >> 1);
                yhi[d0] = ph; ylo[d0] = plo;
                float v2 = fmaxf(acc[mi][ni][2] + bv0, 0.f);
                float v3 = fmaxf(acc[mi][ni][3] + bv1, 0.f);
                split_pack(v2, v3, ph, plo);
                size_t d1 = (size_t)(pr0 + 8) * (M0Q / 2) + (col >> 1);
                yhi[d1] = ph; ylo[d1] = plo;
            }
        }
    } else {
        int bb = p0 >> 13;
#pragma unroll
        for (int mi = 0; mi < 2; mi++) {
#pragma unroll
            for (int ni = 0; ni < 4; ni++) {
                int col = wn * 32 + ni * 8 + t * 2;
                float bv0 = bias[col], bv1 = bias[col + 1];
                int p = p0 + wm * 32 + mi * 16 + g;
                int n = p & (NQ - 1);
                size_t r0 = ((size_t)(bb * M1Q + col)) * NQ;
                size_t r1 = ((size_t)(bb * M1Q + col + 1)) * NQ;
                outF[r0 + n]     = fmaxf(acc[mi][ni][0] + bv0, 0.f);
                outF[r1 + n]     = fmaxf(acc[mi][ni][1] + bv1, 0.f);
                outF[r0 + n + 8] = fmaxf(acc[mi][ni][2] + bv0, 0.f);
                outF[r1 + n + 8] = fmaxf(acc[mi][ni][3] + bv1, 0.f);
            }
        }
    }
}

// ---------------- launch -----------------------------------------------------
extern "C" void kernel_launch(void* const* d_in, const int* in_sizes, int n_in,
                              void* d_out, int out_size) {
    const float* coords_1   = (const float*)d_in[0];
    const float* coords_2   = (const float*)d_in[1];
    const float* features_1 = (const float*)d_in[2];
    const float* features_2 = (const float*)d_in[3];
    const float* w0  = (const float*)d_in[4];
    const float* b0  = (const float*)d_in[5];
    const float* g0  = (const float*)d_in[6];
    const float* be0 = (const float*)d_in[7];
    const float* m0  = (const float*)d_in[8];
    const float* v0  = (const float*)d_in[9];
    const float* w1  = (const float*)d_in[10];
    const float* b1  = (const float*)d_in[11];
    const float* g1  = (const float*)d_in[12];
    const float* be1 = (const float*)d_in[13];
    const float* m1  = (const float*)d_in[14];
    const float* v1  = (const float*)d_in[15];
    float* out = (float*)d_out;

    const int SMEM = 2 * 4 * 128 * 64 * 2;   // 131072 bytes
    const int KSMEM = 32768 + 32896 + 3072 + 3072;  // 71808 bytes
    cudaFuncSetAttribute(mma_gemm_kernel<KX, false>,
                         cudaFuncAttributeMaxDynamicSharedMemorySize, SMEM);
    cudaFuncSetAttribute(mma_gemm_kernel<M0Q, true>,
                         cudaFuncAttributeMaxDynamicSharedMemorySize, SMEM);
    cudaFuncSetAttribute(knng_kernel,
                         cudaFuncAttributeMaxDynamicSharedMemorySize, KSMEM);

    fold0_kernel<<<M0Q, KX>>>(w0, b0, g0, be0, m0, v0);
    fold1_kernel<<<M1Q, M0Q>>>(w1, b1, g1, be1, m1, v1);
    transpose_f2_kernel<<<dim3(SQ / 32, C2Q / 32, BQ), dim3(32, 8)>>>(features_2);
    copy_f1_kernel<<<dim3(NQ / 32, BQ), 256>>>(features_1);
    knng_kernel<<<PQ / 256, 256, KSMEM>>>(coords_1, coords_2);
    mma_gemm_kernel<KX, false><<<dim3(PQ / 128, M0Q / 128), 512, SMEM>>>(out);
    mma_gemm_kernel<M0Q, true><<<dim3(PQ / 128, M1Q / 128), 512, SMEM>>>(out);
}

// round 8
// speedup vs baseline: 1.0815x; 1.0815x over previous
#include <cuda_runtime.h>
#include <cuda_bf16.h>
#include <math.h>
#include <stdint.h>

// Problem constants
#define BQ   16
#define NQ   8192
#define SQ   2048
#define C1Q  128
#define C2Q  256
#define PQ   (BQ * NQ)      // 131072 points
#define KX   384            // C1 + C2 (GEMM1 K)
#define M0Q  256            // layer0 out channels
#define M1Q  128            // layer1 out channels
#define BN_EPS 1e-5f

// ---------------- scratch (static device globals; no cudaMalloc) ------------
__device__ float g_b0f[M0Q];
__device__ float g_b1f[M1Q];
__device__ __nv_bfloat16 g_w0hi[M0Q * KX];
__device__ __nv_bfloat16 g_w0lo[M0Q * KX];
__device__ __nv_bfloat16 g_w1hi[M1Q * M0Q];
__device__ __nv_bfloat16 g_w1lo[M1Q * M0Q];
__device__ float g_f2t[BQ * SQ * C2Q];                  // features_2 transposed [b][s][c]
__device__ __nv_bfloat16 g_xhi[(size_t)PQ * KX];        // X hi, K-major [p][k]
__device__ __nv_bfloat16 g_xlo[(size_t)PQ * KX];
__device__ __nv_bfloat16 g_yhi[(size_t)PQ * M0Q];       // Y hi, K-major [p][m]
__device__ __nv_bfloat16 g_ylo[(size_t)PQ * M0Q];
__device__ int   g_idx[PQ * 3];
__device__ float g_wt[PQ * 3];

// ---------------- PTX helpers (sm_80-level only; NO tcgen05) ----------------
__device__ __forceinline__ uint32_t smem_u32(const void* p) {
    uint32_t r;
    asm("{ .reg .u64 t; cvta.to.shared.u64 t, %1; cvt.u32.u64 %0, t; }" : "=r"(r) : "l"(p));
    return r;
}
__device__ __forceinline__ void cp16(uint32_t dst, const void* src) {
    asm volatile("cp.async.cg.shared.global [%0], [%1], 16;" :: "r"(dst), "l"(src));
}
#define CP_COMMIT() asm volatile("cp.async.commit_group;" ::: "memory")
#define CP_WAIT0()  asm volatile("cp.async.wait_group 0;" ::: "memory")
#define CP_WAIT1()  asm volatile("cp.async.wait_group 1;" ::: "memory")

#define SWZ(o) ((uint32_t)(o) ^ ((((uint32_t)(o)) >> 3) & 0x70u))

__device__ __forceinline__ void ldsm4(uint32_t& r0, uint32_t& r1, uint32_t& r2,
                                      uint32_t& r3, uint32_t addr) {
    asm volatile("ldmatrix.sync.aligned.m8n8.x4.shared.b16 {%0,%1,%2,%3}, [%4];"
                 : "=r"(r0), "=r"(r1), "=r"(r2), "=r"(r3) : "r"(addr));
}
__device__ __forceinline__ void mma16816(float* d, uint32_t a0, uint32_t a1,
                                         uint32_t a2, uint32_t a3,
                                         uint32_t b0, uint32_t b1) {
    asm volatile(
        "mma.sync.aligned.m16n8k16.row.col.f32.bf16.bf16.f32 "
        "{%0,%1,%2,%3}, {%4,%5,%6,%7}, {%8,%9}, {%0,%1,%2,%3};"
        : "+f"(d[0]), "+f"(d[1]), "+f"(d[2]), "+f"(d[3])
        : "r"(a0), "r"(a1), "r"(a2), "r"(a3), "r"(b0), "r"(b1));
}

__device__ __forceinline__ void split_pack(float v0, float v1, uint32_t& ph, uint32_t& plo) {
    __nv_bfloat16 h0 = __float2bfloat16(v0), h1 = __float2bfloat16(v1);
    float r0 = v0 - __bfloat162float(h0), r1 = v1 - __bfloat162float(h1);
    __nv_bfloat16 l0 = __float2bfloat16(r0), l1 = __float2bfloat16(r1);
    ph  = (uint32_t)__bfloat16_as_ushort(h0) | ((uint32_t)__bfloat16_as_ushort(h1) << 16);
    plo = (uint32_t)__bfloat16_as_ushort(l0) | ((uint32_t)__bfloat16_as_ushort(l1) << 16);
}

// ---------------- BN fold + bf16 split ---------------------------------------
__global__ void fold0_kernel(const float* __restrict__ w, const float* __restrict__ b,
                             const float* __restrict__ g, const float* __restrict__ be,
                             const float* __restrict__ m, const float* __restrict__ v) {
    int o = blockIdx.x;
    float s = g[o] * rsqrtf(v[o] + BN_EPS);
    int c = threadIdx.x;
    float val = w[o * KX + c] * s;
    __nv_bfloat16 hi = __float2bfloat16(val);
    g_w0hi[o * KX + c] = hi;
    g_w0lo[o * KX + c] = __float2bfloat16(val - __bfloat162float(hi));
    if (c == 0) g_b0f[o] = (b[o] - m[o]) * s + be[o];
}

__global__ void fold1_kernel(const float* __restrict__ w, const float* __restrict__ b,
                             const float* __restrict__ g, const float* __restrict__ be,
                             const float* __restrict__ m, const float* __restrict__ v) {
    int o = blockIdx.x;
    float s = g[o] * rsqrtf(v[o] + BN_EPS);
    int c = threadIdx.x;
    float val = w[o * M0Q + c] * s;
    __nv_bfloat16 hi = __float2bfloat16(val);
    g_w1hi[o * M0Q + c] = hi;
    g_w1lo[o * M0Q + c] = __float2bfloat16(val - __bfloat162float(hi));
    if (c == 0) g_b1f[o] = (b[o] - m[o]) * s + be[o];
}

// ---------------- transpose features_2: (B,C2,S) -> (B,S,C2) ----------------
__global__ void transpose_f2_kernel(const float* __restrict__ f2) {
    __shared__ float tile[32][33];
    int b  = blockIdx.z;
    int s0 = blockIdx.x * 32;
    int c0 = blockIdx.y * 32;
    int s = s0 + threadIdx.x;
#pragma unroll
    for (int r = 0; r < 4; r++) {
        int c = c0 + threadIdx.y + r * 8;
        tile[threadIdx.y + r * 8][threadIdx.x] = f2[((size_t)b * C2Q + c) * SQ + s];
    }
    __syncthreads();
    int c = c0 + threadIdx.x;
#pragma unroll
    for (int r = 0; r < 4; r++) {
        int s2 = s0 + threadIdx.y + r * 8;
        g_f2t[((size_t)b * SQ + s2) * C2Q + c] = tile[threadIdx.x][threadIdx.y + r * 8];
    }
}

// ---------------- features_1 -> X[p][0..127] bf16 hi/lo ----------------------
__global__ __launch_bounds__(256) void copy_f1_kernel(const float* __restrict__ f1) {
    __shared__ float tile[C1Q][33];
    int b  = blockIdx.y;
    int n0 = blockIdx.x * 32;
    int tid = threadIdx.x;
#pragma unroll
    for (int it = 0; it < 16; it++) {
        int i = tid + it * 256;
        int c = i >> 5, n = i & 31;
        tile[c][n] = f1[((size_t)b * C1Q + c) * NQ + n0 + n];
    }
    __syncthreads();
    uint32_t* xhi = (uint32_t*)g_xhi;
    uint32_t* xlo = (uint32_t*)g_xlo;
#pragma unroll
    for (int it = 0; it < 8; it++) {
        int i = tid + it * 256;
        int nrow = i >> 6, c2 = i & 63;
        uint32_t ph, plo;
        split_pack(tile[c2 * 2][nrow], tile[c2 * 2 + 1][nrow], ph, plo);
        size_t p = (size_t)b * NQ + n0 + nrow;
        xhi[p * (KX / 2) + c2] = ph;
        xlo[p * (KX / 2) + c2] = plo;
    }
}

// ---------------- 3-NN + inverse-distance weights (reference rounding) -------
__global__ __launch_bounds__(256) void knn_kernel(const float* __restrict__ c1,
                                                  const float* __restrict__ c2) {
    __shared__ float4 sc[SQ];
    int b = blockIdx.y;
    const float* cb = c2 + (size_t)b * 3 * SQ;
    for (int i = threadIdx.x; i < SQ; i += 256) {
        float x = cb[i], y = cb[SQ + i], z = cb[2 * SQ + i];
        float sq = __fadd_rn(__fadd_rn(__fmul_rn(x, x), __fmul_rn(y, y)), __fmul_rn(z, z));
        sc[i] = make_float4(x, y, z, sq);
    }
    __syncthreads();

    int n = blockIdx.x * 256 + threadIdx.x;
    const float* qb = c1 + (size_t)b * 3 * NQ;
    float x1 = qb[n], y1 = qb[NQ + n], z1 = qb[2 * NQ + n];
    float q2 = __fadd_rn(__fadd_rn(__fmul_rn(x1, x1), __fmul_rn(y1, y1)), __fmul_rn(z1, z1));

    float d0 = 1e30f, d1 = 1e30f, d2 = 1e30f;
    int   i0 = 0, i1 = 0, i2 = 0;
#pragma unroll 4
    for (int s = 0; s < SQ; s++) {
        float4 c = sc[s];
        float dot = __fadd_rn(__fadd_rn(__fmul_rn(x1, c.x), __fmul_rn(y1, c.y)),
                              __fmul_rn(z1, c.z));
        float d = __fsub_rn(__fadd_rn(q2, c.w), __fadd_rn(dot, dot));
        if (d < d2) {
            if (d < d1) {
                d2 = d1; i2 = i1;
                if (d < d0) { d1 = d0; i1 = i0; d0 = d; i0 = s; }
                else        { d1 = d;  i1 = s; }
            } else { d2 = d; i2 = s; }
        }
    }
    d0 = fmaxf(d0, 1e-10f); d1 = fmaxf(d1, 1e-10f); d2 = fmaxf(d2, 1e-10f);
    float r0 = __fdiv_rn(1.0f, d0), r1 = __fdiv_rn(1.0f, d1), r2 = __fdiv_rn(1.0f, d2);
    float rs = __fadd_rn(__fadd_rn(r0, r1), r2);
    int p = b * NQ + n;
    g_idx[p * 3 + 0] = i0; g_idx[p * 3 + 1] = i1; g_idx[p * 3 + 2] = i2;
    g_wt[p * 3 + 0] = __fdiv_rn(r0, rs);
    g_wt[p * 3 + 1] = __fdiv_rn(r1, rs);
    g_wt[p * 3 + 2] = __fdiv_rn(r2, rs);
}

// ---------------- gather + interpolate -> X[p][128..383] bf16 hi/lo ----------
__global__ __launch_bounds__(256) void gather_kernel() {
    __shared__ float tile[32][257];
    __shared__ int   sidx[32][3];
    __shared__ float swt[32][3];
    int p0 = blockIdx.x * 32;
    int t = threadIdx.x;
    if (t < 96) {
        int pl = t / 3, k = t - pl * 3;
        sidx[pl][k] = g_idx[(p0 + pl) * 3 + k];
        swt[pl][k]  = g_wt[(p0 + pl) * 3 + k];
    }
    __syncthreads();

    int warp = t >> 5, lane = t & 31;
#pragma unroll
    for (int it = 0; it < 4; it++) {
        int pl = warp * 4 + it;
        int p  = p0 + pl;
        int bb = p >> 13;
        const float* base = g_f2t + (size_t)bb * SQ * C2Q;
        const float* fa = base + (size_t)sidx[pl][0] * C2Q;
        const float* fb = base + (size_t)sidx[pl][1] * C2Q;
        const float* fc = base + (size_t)sidx[pl][2] * C2Q;
        float w0 = swt[pl][0], w1 = swt[pl][1], w2 = swt[pl][2];
#pragma unroll
        for (int q = 0; q < 2; q++) {
            int c = lane * 4 + q * 128;
            float4 a = *(const float4*)(fa + c);
            float4 b = *(const float4*)(fb + c);
            float4 cv = *(const float4*)(fc + c);
            tile[pl][c + 0] = __fadd_rn(__fadd_rn(__fmul_rn(a.x, w0), __fmul_rn(b.x, w1)), __fmul_rn(cv.x, w2));
            tile[pl][c + 1] = __fadd_rn(__fadd_rn(__fmul_rn(a.y, w0), __fmul_rn(b.y, w1)), __fmul_rn(cv.y, w2));
            tile[pl][c + 2] = __fadd_rn(__fadd_rn(__fmul_rn(a.z, w0), __fmul_rn(b.z, w1)), __fmul_rn(cv.z, w2));
            tile[pl][c + 3] = __fadd_rn(__fadd_rn(__fmul_rn(a.w, w0), __fmul_rn(b.w, w1)), __fmul_rn(cv.w, w2));
        }
    }
    __syncthreads();

    uint32_t* xhi = (uint32_t*)g_xhi;
    uint32_t* xlo = (uint32_t*)g_xlo;
#pragma unroll
    for (int it = 0; it < 16; it++) {
        int i = t + it * 256;
        int pl = i >> 7, c2 = i & 127;
        uint32_t ph, plo;
        split_pack(tile[pl][c2 * 2], tile[pl][c2 * 2 + 1], ph, plo);
        size_t p = (size_t)(p0 + pl);
        xhi[p * (KX / 2) + 64 + c2] = ph;
        xlo[p * (KX / 2) + 64 + c2] = plo;
    }
}

// ---------------- mma.sync bf16x3 GEMM ----------------------------------------
// Same structure as the proven 553us version; ONLY the grid mapping changed:
// blockIdx.x = N-block (fastest) so launch-adjacent CTAs share the same A tile
// and the second read hits L2 instead of DRAM.
template <int KDIM, bool FINAL>
__global__ __launch_bounds__(256, 1) void mma_gemm_kernel(float* __restrict__ outF) {
    constexpr int NCH   = KDIM / 64;
    constexpr int TILE  = 128 * 64 * 2;      // 16 KB (one matrix half-chunk)
    constexpr int CHUNK = 4 * TILE;          // Ahi, Alo, Whi, Wlo = 64 KB

    const __nv_bfloat16* Ahi = FINAL ? g_yhi : g_xhi;
    const __nv_bfloat16* Alo = FINAL ? g_ylo : g_xlo;
    const __nv_bfloat16* Whi = FINAL ? g_w1hi : g_w0hi;
    const __nv_bfloat16* Wlo = FINAL ? g_w1lo : g_w0lo;
    const float* bias = FINAL ? g_b1f : g_b0f;

    extern __shared__ __align__(1024) char dsm[];
    const uint32_t s0 = smem_u32(dsm);

    const int tid  = threadIdx.x;
    const int warp = tid >> 5;
    const int lane = tid & 31;
    const int wm   = warp >> 2;              // 0..1
    const int wn   = warp & 3;               // 0..3
    const int p0   = blockIdx.y * 128;       // point block (slow index)
    const int n0   = blockIdx.x * 128;       // channel block (fast index)

    const int a_row = (lane & 15);
    const int a_k8  = (lane >> 4) * 8;
    const int b_row = ((lane >> 4) & 1) * 8 + (lane & 7);
    const int b_k8  = ((lane >> 3) & 1) * 8;

    float acc[4][4][4];
#pragma unroll
    for (int mi = 0; mi < 4; mi++)
#pragma unroll
        for (int ni = 0; ni < 4; ni++)
#pragma unroll
            for (int e = 0; e < 4; e++) acc[mi][ni][e] = 0.0f;

    auto load_chunk = [&](int buf, int ch) {
        const uint32_t base = s0 + buf * CHUNK;
        const size_t rs = (size_t)KDIM * 2;  // row stride bytes
        const char* gAh = (const char*)Ahi + (size_t)p0 * rs + (size_t)ch * 128;
        const char* gAl = (const char*)Alo + (size_t)p0 * rs + (size_t)ch * 128;
        const char* gWh = (const char*)Whi + (size_t)n0 * rs + (size_t)ch * 128;
        const char* gWl = (const char*)Wlo + (size_t)n0 * rs + (size_t)ch * 128;
#pragma unroll
        for (int it = 0; it < 4; it++) {
            int i = tid + it * 256;          // 0..1023
            int row = i >> 3, c16 = (i & 7) * 16;
            uint32_t sw = SWZ(row * 128 + c16);
            size_t go = (size_t)row * rs + c16;
            cp16(base + sw,            gAh + go);
            cp16(base + TILE + sw,     gAl + go);
            cp16(base + 2 * TILE + sw, gWh + go);
            cp16(base + 3 * TILE + sw, gWl + go);
        }
        CP_COMMIT();
    };

    load_chunk(0, 0);
    load_chunk(1, 1);

    for (int c = 0; c < NCH; c++) {
        if (c + 1 < NCH) { CP_WAIT1(); } else { CP_WAIT0(); }
        __syncthreads();

        const uint32_t base = s0 + (c & 1) * CHUNK;
#pragma unroll
        for (int kk = 0; kk < 4; kk++) {
            const int kb = (kk * 16 + a_k8) * 2;
            uint32_t ah[4][4], al[4][4];
#pragma unroll
            for (int mi = 0; mi < 4; mi++) {
                uint32_t off = SWZ((wm * 64 + mi * 16 + a_row) * 128 + kb);
                ldsm4(ah[mi][0], ah[mi][1], ah[mi][2], ah[mi][3], base + off);
                ldsm4(al[mi][0], al[mi][1], al[mi][2], al[mi][3], base + TILE + off);
            }
            uint32_t bh[4][2], bl[4][2];
            const int kbB = (kk * 16 + b_k8) * 2;
#pragma unroll
            for (int nip = 0; nip < 2; nip++) {
                uint32_t off = SWZ((wn * 32 + nip * 16 + b_row) * 128 + kbB);
                ldsm4(bh[2 * nip][0], bh[2 * nip][1], bh[2 * nip + 1][0], bh[2 * nip + 1][1],
                      base + 2 * TILE + off);
                ldsm4(bl[2 * nip][0], bl[2 * nip][1], bl[2 * nip + 1][0], bl[2 * nip + 1][1],
                      base + 3 * TILE + off);
            }
#pragma unroll
            for (int mi = 0; mi < 4; mi++)
#pragma unroll
                for (int ni = 0; ni < 4; ni++) {
                    mma16816(acc[mi][ni], ah[mi][0], ah[mi][1], ah[mi][2], ah[mi][3],
                             bh[ni][0], bh[ni][1]);
                    mma16816(acc[mi][ni], al[mi][0], al[mi][1], al[mi][2], al[mi][3],
                             bh[ni][0], bh[ni][1]);
                    mma16816(acc[mi][ni], ah[mi][0], ah[mi][1], ah[mi][2], ah[mi][3],
                             bl[ni][0], bl[ni][1]);
                }
        }

        if (c + 2 < NCH) {
            __syncthreads();
            load_chunk(c & 1, c + 2);
        }
    }

    // ---------------- epilogue -------------------------------------------------
    const int g = lane >> 2, t = lane & 3;
    if (!FINAL) {
        uint32_t* yhi = (uint32_t*)g_yhi;
        uint32_t* ylo = (uint32_t*)g_ylo;
#pragma unroll
        for (int mi = 0; mi < 4; mi++) {
#pragma unroll
            for (int ni = 0; ni < 4; ni++) {
                int col = n0 + wn * 32 + ni * 8 + t * 2;
                float bv0 = bias[col];
                float bv1 = bias[col + 1];
                int pr0 = p0 + wm * 64 + mi * 16 + g;
                float v0 = fmaxf(acc[mi][ni][0] + bv0, 0.f);
                float v1 = fmaxf(acc[mi][ni][1] + bv1, 0.f);
                uint32_t ph, plo;
                split_pack(v0, v1, ph, plo);
                size_t d0 = (size_t)pr0 * (M0Q / 2) + (col >> 1);
                yhi[d0] = ph; ylo[d0] = plo;
                float v2 = fmaxf(acc[mi][ni][2] + bv0, 0.f);
                float v3 = fmaxf(acc[mi][ni][3] + bv1, 0.f);
                split_pack(v2, v3, ph, plo);
                size_t d1 = (size_t)(pr0 + 8) * (M0Q / 2) + (col >> 1);
                yhi[d1] = ph; ylo[d1] = plo;
            }
        }
    } else {
        int bb = p0 >> 13;
#pragma unroll
        for (int mi = 0; mi < 4; mi++) {
#pragma unroll
            for (int ni = 0; ni < 4; ni++) {
                int col = wn * 32 + ni * 8 + t * 2;
                float bv0 = bias[col], bv1 = bias[col + 1];
                int p = p0 + wm * 64 + mi * 16 + g;
                int n = p & (NQ - 1);
                size_t r0 = ((size_t)(bb * M1Q + col)) * NQ;
                size_t r1 = ((size_t)(bb * M1Q + col + 1)) * NQ;
                outF[r0 + n]     = fmaxf(acc[mi][ni][0] + bv0, 0.f);
                outF[r1 + n]     = fmaxf(acc[mi][ni][1] + bv1, 0.f);
                outF[r0 + n + 8] = fmaxf(acc[mi][ni][2] + bv0, 0.f);
                outF[r1 + n + 8] = fmaxf(acc[mi][ni][3] + bv1, 0.f);
            }
        }
    }
}

// ---------------- launch -----------------------------------------------------
extern "C" void kernel_launch(void* const* d_in, const int* in_sizes, int n_in,
                              void* d_out, int out_size) {
    const float* coords_1   = (const float*)d_in[0];
    const float* coords_2   = (const float*)d_in[1];
    const float* features_1 = (const float*)d_in[2];
    const float* features_2 = (const float*)d_in[3];
    const float* w0  = (const float*)d_in[4];
    const float* b0  = (const float*)d_in[5];
    const float* g0  = (const float*)d_in[6];
    const float* be0 = (const float*)d_in[7];
    const float* m0  = (const float*)d_in[8];
    const float* v0  = (const float*)d_in[9];
    const float* w1  = (const float*)d_in[10];
    const float* b1  = (const float*)d_in[11];
    const float* g1  = (const float*)d_in[12];
    const float* be1 = (const float*)d_in[13];
    const float* m1  = (const float*)d_in[14];
    const float* v1  = (const float*)d_in[15];
    float* out = (float*)d_out;

    const int SMEM = 2 * 4 * 128 * 64 * 2;   // 131072 bytes
    cudaFuncSetAttribute(mma_gemm_kernel<KX, false>,
                         cudaFuncAttributeMaxDynamicSharedMemorySize, SMEM);
    cudaFuncSetAttribute(mma_gemm_kernel<M0Q, true>,
                         cudaFuncAttributeMaxDynamicSharedMemorySize, SMEM);

    fold0_kernel<<<M0Q, KX>>>(w0, b0, g0, be0, m0, v0);
    fold1_kernel<<<M1Q, M0Q>>>(w1, b1, g1, be1, m1, v1);
    transpose_f2_kernel<<<dim3(SQ / 32, C2Q / 32, BQ), dim3(32, 8)>>>(features_2);
    copy_f1_kernel<<<dim3(NQ / 32, BQ), 256>>>(features_1);
    knn_kernel<<<dim3(NQ / 256, BQ), 256>>>(coords_1, coords_2);
    gather_kernel<<<PQ / 32, 256>>>();
    // N-block fastest: CTAs sharing an A tile are launch-adjacent -> L2 reuse
    mma_gemm_kernel<KX, false><<<dim3(M0Q / 128, PQ / 128), 256, SMEM>>>(out);
    mma_gemm_kernel<M0Q, true><<<dim3(M1Q / 128, PQ / 128), 256, SMEM>>>(out);
}

// round 10
// speedup vs baseline: 1.0900x; 1.0078x over previous
#include <cuda_runtime.h>
#include <cuda_bf16.h>
#include <math.h>
#include <stdint.h>

// Problem constants
#define BQ   16
#define NQ   8192
#define SQ   2048
#define C1Q  128
#define C2Q  256
#define PQ   (BQ * NQ)      // 131072 points
#define KX   384            // C1 + C2 (GEMM1 K)
#define M0Q  256            // layer0 out channels
#define M1Q  128            // layer1 out channels
#define BN_EPS 1e-5f

// ---------------- scratch (static device globals; no cudaMalloc) ------------
__device__ float g_b0f[M0Q];
__device__ float g_b1f[M1Q];
__device__ __nv_bfloat16 g_w0hi[M0Q * KX];
__device__ __nv_bfloat16 g_w0lo[M0Q * KX];
__device__ __nv_bfloat16 g_w1hi[M1Q * M0Q];
__device__ __nv_bfloat16 g_w1lo[M1Q * M0Q];
__device__ float g_f2t[BQ * SQ * C2Q];                  // features_2 transposed [b][s][c]
__device__ __nv_bfloat16 g_xhi[(size_t)PQ * KX];        // X hi, K-major [p][k]
__device__ __nv_bfloat16 g_xlo[(size_t)PQ * KX];
__device__ __nv_bfloat16 g_yhi[(size_t)PQ * M0Q];       // Y hi, K-major [p][m]
__device__ __nv_bfloat16 g_ylo[(size_t)PQ * M0Q];
__device__ int   g_idx[PQ * 3];
__device__ float g_wt[PQ * 3];

// ---------------- PTX helpers (sm_80-level only; NO tcgen05) ----------------
__device__ __forceinline__ uint32_t smem_u32(const void* p) {
    uint32_t r;
    asm("{ .reg .u64 t; cvta.to.shared.u64 t, %1; cvt.u32.u64 %0, t; }" : "=r"(r) : "l"(p));
    return r;
}
__device__ __forceinline__ void cp16(uint32_t dst, const void* src) {
    asm volatile("cp.async.cg.shared.global [%0], [%1], 16;" :: "r"(dst), "l"(src));
}
#define CP_COMMIT() asm volatile("cp.async.commit_group;" ::: "memory")
#define CP_WAIT0()  asm volatile("cp.async.wait_group 0;" ::: "memory")
#define CP_WAIT1()  asm volatile("cp.async.wait_group 1;" ::: "memory")

#define SWZ(o) ((uint32_t)(o) ^ ((((uint32_t)(o)) >> 3) & 0x70u))

__device__ __forceinline__ void ldsm4(uint32_t& r0, uint32_t& r1, uint32_t& r2,
                                      uint32_t& r3, uint32_t addr) {
    asm volatile("ldmatrix.sync.aligned.m8n8.x4.shared.b16 {%0,%1,%2,%3}, [%4];"
                 : "=r"(r0), "=r"(r1), "=r"(r2), "=r"(r3) : "r"(addr));
}
__device__ __forceinline__ void mma16816(float* d, uint32_t a0, uint32_t a1,
                                         uint32_t a2, uint32_t a3,
                                         uint32_t b0, uint32_t b1) {
    asm volatile(
        "mma.sync.aligned.m16n8k16.row.col.f32.bf16.bf16.f32 "
        "{%0,%1,%2,%3}, {%4,%5,%6,%7}, {%8,%9}, {%0,%1,%2,%3};"
        : "+f"(d[0]), "+f"(d[1]), "+f"(d[2]), "+f"(d[3])
        : "r"(a0), "r"(a1), "r"(a2), "r"(a3), "r"(b0), "r"(b1));
}

__device__ __forceinline__ void split_pack(float v0, float v1, uint32_t& ph, uint32_t& plo) {
    __nv_bfloat16 h0 = __float2bfloat16(v0), h1 = __float2bfloat16(v1);
    float r0 = v0 - __bfloat162float(h0), r1 = v1 - __bfloat162float(h1);
    __nv_bfloat16 l0 = __float2bfloat16(r0), l1 = __float2bfloat16(r1);
    ph  = (uint32_t)__bfloat16_as_ushort(h0) | ((uint32_t)__bfloat16_as_ushort(h1) << 16);
    plo = (uint32_t)__bfloat16_as_ushort(l0) | ((uint32_t)__bfloat16_as_ushort(l1) << 16);
}

// ---------------- transpose features_2 + BN folds (merged) -------------------
// blockIdx.x < 64 : transpose one 32x32 tile of features_2 (B,C2,S)->(B,S,C2)
// blockIdx.x == 64: fold BN into weights + bf16 hi/lo split (both layers)
__global__ void transpose_fold_kernel(const float* __restrict__ f2,
                                      const float* __restrict__ w0, const float* __restrict__ b0,
                                      const float* __restrict__ g0, const float* __restrict__ be0,
                                      const float* __restrict__ m0, const float* __restrict__ v0,
                                      const float* __restrict__ w1, const float* __restrict__ b1,
                                      const float* __restrict__ g1, const float* __restrict__ be1,
                                      const float* __restrict__ m1, const float* __restrict__ v1) {
    if (blockIdx.x == 64) {
        // FIX (R9 bug): flatten the 2-D (32,8) block correctly
        int tid  = threadIdx.y * 32 + threadIdx.x;                      // 0..255
        int base = (blockIdx.y * 16 + blockIdx.z) * 256 + tid;          // 0..32767
        // fold layer0: 256*384 = 98304 elements
        for (int e = base; e < M0Q * KX; e += 32768) {
            int o = e / KX;
            float s = g0[o] * rsqrtf(v0[o] + BN_EPS);
            float val = w0[e] * s;
            __nv_bfloat16 hi = __float2bfloat16(val);
            g_w0hi[e] = hi;
            g_w0lo[e] = __float2bfloat16(val - __bfloat162float(hi));
        }
        // fold layer1: 128*256 = 32768 elements (exactly one per thread)
        {
            int e = base;
            int o = e >> 8;
            float s = g1[o] * rsqrtf(v1[o] + BN_EPS);
            float val = w1[e] * s;
            __nv_bfloat16 hi = __float2bfloat16(val);
            g_w1hi[e] = hi;
            g_w1lo[e] = __float2bfloat16(val - __bfloat162float(hi));
        }
        if (base < M0Q) {
            float s = g0[base] * rsqrtf(v0[base] + BN_EPS);
            g_b0f[base] = (b0[base] - m0[base]) * s + be0[base];
        }
        if (base < M1Q) {
            float s = g1[base] * rsqrtf(v1[base] + BN_EPS);
            g_b1f[base] = (b1[base] - m1[base]) * s + be1[base];
        }
        return;
    }
    __shared__ float tile[32][33];
    int b  = blockIdx.z;
    int s0 = blockIdx.x * 32;
    int c0 = blockIdx.y * 32;
    int tx = threadIdx.x, ty = threadIdx.y;
    int s = s0 + tx;
#pragma unroll
    for (int r = 0; r < 4; r++) {
        int c = c0 + ty + r * 8;
        tile[ty + r * 8][tx] = f2[((size_t)b * C2Q + c) * SQ + s];
    }
    __syncthreads();
    int c = c0 + tx;
#pragma unroll
    for (int r = 0; r < 4; r++) {
        int s2 = s0 + ty + r * 8;
        g_f2t[((size_t)b * SQ + s2) * C2Q + c] = tile[tx][ty + r * 8];
    }
}

// ---------------- 3-NN + inverse-distance weights (reference rounding) -------
__global__ __launch_bounds__(256) void knn_kernel(const float* __restrict__ c1,
                                                  const float* __restrict__ c2) {
    __shared__ float4 sc[SQ];
    int b = blockIdx.y;
    const float* cb = c2 + (size_t)b * 3 * SQ;
    for (int i = threadIdx.x; i < SQ; i += 256) {
        float x = cb[i], y = cb[SQ + i], z = cb[2 * SQ + i];
        float sq = __fadd_rn(__fadd_rn(__fmul_rn(x, x), __fmul_rn(y, y)), __fmul_rn(z, z));
        sc[i] = make_float4(x, y, z, sq);
    }
    __syncthreads();

    int n = blockIdx.x * 256 + threadIdx.x;
    const float* qb = c1 + (size_t)b * 3 * NQ;
    float x1 = qb[n], y1 = qb[NQ + n], z1 = qb[2 * NQ + n];
    float q2 = __fadd_rn(__fadd_rn(__fmul_rn(x1, x1), __fmul_rn(y1, y1)), __fmul_rn(z1, z1));

    float d0 = 1e30f, d1 = 1e30f, d2 = 1e30f;
    int   i0 = 0, i1 = 0, i2 = 0;
#pragma unroll 4
    for (int s = 0; s < SQ; s++) {
        float4 c = sc[s];
        float dot = __fadd_rn(__fadd_rn(__fmul_rn(x1, c.x), __fmul_rn(y1, c.y)),
                              __fmul_rn(z1, c.z));
        float d = __fsub_rn(__fadd_rn(q2, c.w), __fadd_rn(dot, dot));
        if (d < d2) {
            if (d < d1) {
                d2 = d1; i2 = i1;
                if (d < d0) { d1 = d0; i1 = i0; d0 = d; i0 = s; }
                else        { d1 = d;  i1 = s; }
            } else { d2 = d; i2 = s; }
        }
    }
    d0 = fmaxf(d0, 1e-10f); d1 = fmaxf(d1, 1e-10f); d2 = fmaxf(d2, 1e-10f);
    float r0 = __fdiv_rn(1.0f, d0), r1 = __fdiv_rn(1.0f, d1), r2 = __fdiv_rn(1.0f, d2);
    float rs = __fadd_rn(__fadd_rn(r0, r1), r2);
    int p = b * NQ + n;
    g_idx[p * 3 + 0] = i0; g_idx[p * 3 + 1] = i1; g_idx[p * 3 + 2] = i2;
    g_wt[p * 3 + 0] = __fdiv_rn(r0, rs);
    g_wt[p * 3 + 1] = __fdiv_rn(r1, rs);
    g_wt[p * 3 + 2] = __fdiv_rn(r2, rs);
}

// ---------------- buildX: gather/interpolate + f1 copy -> X bf16 hi/lo -------
// One block per 32 points. Phase A: gather features_2 via 3-NN indices,
// interpolate, store X K-cols [128,384). Phase B: copy features_1 through the
// same SMEM tile, store X K-cols [0,128). All stores coalesced.
__global__ __launch_bounds__(256) void buildx_kernel(const float* __restrict__ f1) {
    __shared__ float tile[32][257];
    __shared__ int   sidx[32][3];
    __shared__ float swt[32][3];
    int p0 = blockIdx.x * 32;
    int b  = p0 >> 13;
    int n0 = p0 & (NQ - 1);
    int t = threadIdx.x;
    if (t < 96) {
        int pl = t / 3, k = t - pl * 3;
        sidx[pl][k] = g_idx[(p0 + pl) * 3 + k];
        swt[pl][k]  = g_wt[(p0 + pl) * 3 + k];
    }
    __syncthreads();

    uint32_t* xhi = (uint32_t*)g_xhi;
    uint32_t* xlo = (uint32_t*)g_xlo;
    int warp = t >> 5, lane = t & 31;

    // ---- phase A: gather + interpolate ----
    const float* fbase = g_f2t + (size_t)b * SQ * C2Q;
#pragma unroll
    for (int it = 0; it < 4; it++) {
        int pl = warp * 4 + it;
        const float* fa = fbase + (size_t)sidx[pl][0] * C2Q;
        const float* fb = fbase + (size_t)sidx[pl][1] * C2Q;
        const float* fc = fbase + (size_t)sidx[pl][2] * C2Q;
        float w0 = swt[pl][0], w1 = swt[pl][1], w2 = swt[pl][2];
#pragma unroll
        for (int q = 0; q < 2; q++) {
            int c = lane * 4 + q * 128;
            float4 a = *(const float4*)(fa + c);
            float4 bb = *(const float4*)(fb + c);
            float4 cv = *(const float4*)(fc + c);
            tile[pl][c + 0] = __fadd_rn(__fadd_rn(__fmul_rn(a.x, w0), __fmul_rn(bb.x, w1)), __fmul_rn(cv.x, w2));
            tile[pl][c + 1] = __fadd_rn(__fadd_rn(__fmul_rn(a.y, w0), __fmul_rn(bb.y, w1)), __fmul_rn(cv.y, w2));
            tile[pl][c + 2] = __fadd_rn(__fadd_rn(__fmul_rn(a.z, w0), __fmul_rn(bb.z, w1)), __fmul_rn(cv.z, w2));
            tile[pl][c + 3] = __fadd_rn(__fadd_rn(__fmul_rn(a.w, w0), __fmul_rn(bb.w, w1)), __fmul_rn(cv.w, w2));
        }
    }
    __syncthreads();
#pragma unroll
    for (int it = 0; it < 16; it++) {
        int i = t + it * 256;
        int pl = i >> 7, c2 = i & 127;
        uint32_t ph, plo;
        split_pack(tile[pl][c2 * 2], tile[pl][c2 * 2 + 1], ph, plo);
        size_t p = (size_t)(p0 + pl);
        xhi[p * (KX / 2) + 64 + c2] = ph;
        xlo[p * (KX / 2) + 64 + c2] = plo;
    }
    __syncthreads();

    // ---- phase B: features_1 copy through tile ----
#pragma unroll
    for (int it = 0; it < 16; it++) {
        int i = t + it * 256;            // 0..4095
        int c = i >> 5, n = i & 31;
        tile[n][c] = f1[((size_t)b * C1Q + c) * NQ + n0 + n];
    }
    __syncthreads();
#pragma unroll
    for (int it = 0; it < 8; it++) {
        int i = t + it * 256;            // 0..2047
        int pl = i >> 6, c2 = i & 63;
        uint32_t ph, plo;
        split_pack(tile[pl][c2 * 2], tile[pl][c2 * 2 + 1], ph, plo);
        size_t p = (size_t)(p0 + pl);
        xhi[p * (KX / 2) + c2] = ph;
        xlo[p * (KX / 2) + c2] = plo;
    }
}

// ---------------- mma.sync bf16x3 GEMM (unchanged from R8) --------------------
template <int KDIM, bool FINAL>
__global__ __launch_bounds__(256, 1) void mma_gemm_kernel(float* __restrict__ outF) {
    constexpr int NCH   = KDIM / 64;
    constexpr int TILE  = 128 * 64 * 2;      // 16 KB (one matrix half-chunk)
    constexpr int CHUNK = 4 * TILE;          // Ahi, Alo, Whi, Wlo = 64 KB

    const __nv_bfloat16* Ahi = FINAL ? g_yhi : g_xhi;
    const __nv_bfloat16* Alo = FINAL ? g_ylo : g_xlo;
    const __nv_bfloat16* Whi = FINAL ? g_w1hi : g_w0hi;
    const __nv_bfloat16* Wlo = FINAL ? g_w1lo : g_w0lo;
    const float* bias = FINAL ? g_b1f : g_b0f;

    extern __shared__ __align__(1024) char dsm[];
    const uint32_t s0 = smem_u32(dsm);

    const int tid  = threadIdx.x;
    const int warp = tid >> 5;
    const int lane = tid & 31;
    const int wm   = warp >> 2;              // 0..1
    const int wn   = warp & 3;               // 0..3
    const int p0   = blockIdx.y * 128;       // point block (slow index)
    const int n0   = blockIdx.x * 128;       // channel block (fast index)

    const int a_row = (lane & 15);
    const int a_k8  = (lane >> 4) * 8;
    const int b_row = ((lane >> 4) & 1) * 8 + (lane & 7);
    const int b_k8  = ((lane >> 3) & 1) * 8;

    float acc[4][4][4];
#pragma unroll
    for (int mi = 0; mi < 4; mi++)
#pragma unroll
        for (int ni = 0; ni < 4; ni++)
#pragma unroll
            for (int e = 0; e < 4; e++) acc[mi][ni][e] = 0.0f;

    auto load_chunk = [&](int buf, int ch) {
        const uint32_t base = s0 + buf * CHUNK;
        const size_t rs = (size_t)KDIM * 2;  // row stride bytes
        const char* gAh = (const char*)Ahi + (size_t)p0 * rs + (size_t)ch * 128;
        const char* gAl = (const char*)Alo + (size_t)p0 * rs + (size_t)ch * 128;
        const char* gWh = (const char*)Whi + (size_t)n0 * rs + (size_t)ch * 128;
        const char* gWl = (const char*)Wlo + (size_t)n0 * rs + (size_t)ch * 128;
#pragma unroll
        for (int it = 0; it < 4; it++) {
            int i = tid + it * 256;          // 0..1023
            int row = i >> 3, c16 = (i & 7) * 16;
            uint32_t sw = SWZ(row * 128 + c16);
            size_t go = (size_t)row * rs + c16;
            cp16(base + sw,            gAh + go);
            cp16(base + TILE + sw,     gAl + go);
            cp16(base + 2 * TILE + sw, gWh + go);
            cp16(base + 3 * TILE + sw, gWl + go);
        }
        CP_COMMIT();
    };

    load_chunk(0, 0);
    load_chunk(1, 1);

    for (int c = 0; c < NCH; c++) {
        if (c + 1 < NCH) { CP_WAIT1(); } else { CP_WAIT0(); }
        __syncthreads();

        const uint32_t base = s0 + (c & 1) * CHUNK;
#pragma unroll
        for (int kk = 0; kk < 4; kk++) {
            const int kb = (kk * 16 + a_k8) * 2;
            uint32_t ah[4][4], al[4][4];
#pragma unroll
            for (int mi = 0; mi < 4; mi++) {
                uint32_t off = SWZ((wm * 64 + mi * 16 + a_row) * 128 + kb);
                ldsm4(ah[mi][0], ah[mi][1], ah[mi][2], ah[mi][3], base + off);
                ldsm4(al[mi][0], al[mi][1], al[mi][2], al[mi][3], base + TILE + off);
            }
            uint32_t bh[4][2], bl[4][2];
            const int kbB = (kk * 16 + b_k8) * 2;
#pragma unroll
            for (int nip = 0; nip < 2; nip++) {
                uint32_t off = SWZ((wn * 32 + nip * 16 + b_row) * 128 + kbB);
                ldsm4(bh[2 * nip][0], bh[2 * nip][1], bh[2 * nip + 1][0], bh[2 * nip + 1][1],
                      base + 2 * TILE + off);
                ldsm4(bl[2 * nip][0], bl[2 * nip][1], bl[2 * nip + 1][0], bl[2 * nip + 1][1],
                      base + 3 * TILE + off);
            }
#pragma unroll
            for (int mi = 0; mi < 4; mi++)
#pragma unroll
                for (int ni = 0; ni < 4; ni++) {
                    mma16816(acc[mi][ni], ah[mi][0], ah[mi][1], ah[mi][2], ah[mi][3],
                             bh[ni][0], bh[ni][1]);
                    mma16816(acc[mi][ni], al[mi][0], al[mi][1], al[mi][2], al[mi][3],
                             bh[ni][0], bh[ni][1]);
                    mma16816(acc[mi][ni], ah[mi][0], ah[mi][1], ah[mi][2], ah[mi][3],
                             bl[ni][0], bl[ni][1]);
                }
        }

        if (c + 2 < NCH) {
            __syncthreads();
            load_chunk(c & 1, c + 2);
        }
    }

    // ---------------- epilogue -------------------------------------------------
    const int g = lane >> 2, t = lane & 3;
    if (!FINAL) {
        uint32_t* yhi = (uint32_t*)g_yhi;
        uint32_t* ylo = (uint32_t*)g_ylo;
#pragma unroll
        for (int mi = 0; mi < 4; mi++) {
#pragma unroll
            for (int ni = 0; ni < 4; ni++) {
                int col = n0 + wn * 32 + ni * 8 + t * 2;
                float bv0 = bias[col];
                float bv1 = bias[col + 1];
                int pr0 = p0 + wm * 64 + mi * 16 + g;
                float v0 = fmaxf(acc[mi][ni][0] + bv0, 0.f);
                float v1 = fmaxf(acc[mi][ni][1] + bv1, 0.f);
                uint32_t ph, plo;
                split_pack(v0, v1, ph, plo);
                size_t d0 = (size_t)pr0 * (M0Q / 2) + (col >> 1);
                yhi[d0] = ph; ylo[d0] = plo;
                float v2 = fmaxf(acc[mi][ni][2] + bv0, 0.f);
                float v3 = fmaxf(acc[mi][ni][3] + bv1, 0.f);
                split_pack(v2, v3, ph, plo);
                size_t d1 = (size_t)(pr0 + 8) * (M0Q / 2) + (col >> 1);
                yhi[d1] = ph; ylo[d1] = plo;
            }
        }
    } else {
        int bb = p0 >> 13;
#pragma unroll
        for (int mi = 0; mi < 4; mi++) {
#pragma unroll
            for (int ni = 0; ni < 4; ni++) {
                int col = wn * 32 + ni * 8 + t * 2;
                float bv0 = bias[col], bv1 = bias[col + 1];
                int p = p0 + wm * 64 + mi * 16 + g;
                int n = p & (NQ - 1);
                size_t r0 = ((size_t)(bb * M1Q + col)) * NQ;
                size_t r1 = ((size_t)(bb * M1Q + col + 1)) * NQ;
                outF[r0 + n]     = fmaxf(acc[mi][ni][0] + bv0, 0.f);
                outF[r1 + n]     = fmaxf(acc[mi][ni][1] + bv1, 0.f);
                outF[r0 + n + 8] = fmaxf(acc[mi][ni][2] + bv0, 0.f);
                outF[r1 + n + 8] = fmaxf(acc[mi][ni][3] + bv1, 0.f);
            }
        }
    }
}

// ---------------- launch -----------------------------------------------------
extern "C" void kernel_launch(void* const* d_in, const int* in_sizes, int n_in,
                              void* d_out, int out_size) {
    const float* coords_1   = (const float*)d_in[0];
    const float* coords_2   = (const float*)d_in[1];
    const float* features_1 = (const float*)d_in[2];
    const float* features_2 = (const float*)d_in[3];
    const float* w0  = (const float*)d_in[4];
    const float* b0  = (const float*)d_in[5];
    const float* g0  = (const float*)d_in[6];
    const float* be0 = (const float*)d_in[7];
    const float* m0  = (const float*)d_in[8];
    const float* v0  = (const float*)d_in[9];
    const float* w1  = (const float*)d_in[10];
    const float* b1  = (const float*)d_in[11];
    const float* g1  = (const float*)d_in[12];
    const float* be1 = (const float*)d_in[13];
    const float* m1  = (const float*)d_in[14];
    const float* v1  = (const float*)d_in[15];
    float* out = (float*)d_out;

    const int SMEM = 2 * 4 * 128 * 64 * 2;   // 131072 bytes
    cudaFuncSetAttribute(mma_gemm_kernel<KX, false>,
                         cudaFuncAttributeMaxDynamicSharedMemorySize, SMEM);
    cudaFuncSetAttribute(mma_gemm_kernel<M0Q, true>,
                         cudaFuncAttributeMaxDynamicSharedMemorySize, SMEM);

    // 1: transpose + folds
    transpose_fold_kernel<<<dim3(65, 8, 16), dim3(32, 8)>>>(
        features_2, w0, b0, g0, be0, m0, v0, w1, b1, g1, be1, m1, v1);
    // 2: knn
    knn_kernel<<<dim3(NQ / 256, BQ), 256>>>(coords_1, coords_2);
    // 3: buildX (gather + f1 copy)
    buildx_kernel<<<PQ / 32, 256>>>(features_1);
    // 4: gemm1  <-- profiled slot
    mma_gemm_kernel<KX, false><<<dim3(M0Q / 128, PQ / 128), 256, SMEM>>>(out);
    // 5: gemm2
    mma_gemm_kernel<M0Q, true><<<dim3(M1Q / 128, PQ / 128), 256, SMEM>>>(out);
}